// round 1
// baseline (speedup 1.0000x reference)
#include <cuda_runtime.h>
#include <math.h>

// Problem-size maxima (B=4096, D=512 for this dataset)
#define B_MAX 4096
#define D_MAX 512
#define MAXM  256   // max positives per row we track (expected ~2-16)

__device__ float g_Vn[B_MAX * D_MAX];   // normalized vision
__device__ float g_Tn[B_MAX * D_MAX];   // normalized text
__device__ int   g_mid[B_MAX];          // match ids as int32
__device__ float g_mpv[B_MAX];          // mean positive sim, v2t anchors (rows)
__device__ float g_mpt[B_MAX];          // mean positive sim, t2v anchors (cols)
__device__ float g_negv[B_MAX];         // weighted exp-sum of negatives, v2t
__device__ float g_negt[B_MAX];         // weighted exp-sum of negatives, t2v
__device__ float g_loss;
__device__ int   g_npos;

__constant__ float c_INV_T   = 1.0f / 0.07f;
__constant__ float c_MARGIN  = 0.2f;

// ---------------------------------------------------------------------------
// K0: detect id dtype (int64 vs int32) and convert to int32; zero scalars.
// int64 values are in [0,2048) so every odd 32-bit word is 0; for int32 data
// the odd words are themselves random ids — P(all zero) ~ (1/2048)^64 ≈ 0.
// ---------------------------------------------------------------------------
__global__ void k_ids(const unsigned int* __restrict__ raw, int B) {
    __shared__ int s_is64;
    int tid = threadIdx.x;
    if (tid == 0) s_is64 = 1;
    __syncthreads();
    int nchk = min(B / 2, 128);           // safe even if data is int32 (B words)
    for (int i = tid; i < nchk; i += blockDim.x) {
        if (raw[2 * i + 1] != 0u) atomicExch(&s_is64, 0);
    }
    __syncthreads();
    bool is64 = (s_is64 != 0);
    for (int i = tid; i < B; i += blockDim.x) {
        long long v = is64 ? ((const long long*)raw)[i]
                           : (long long)((const int*)raw)[i];
        g_mid[i] = (int)v;
    }
    if (tid == 0) { g_loss = 0.0f; g_npos = 0; }
}

__global__ void k_zero(int B) {
    int i = blockIdx.x * blockDim.x + threadIdx.x;
    if (i < B) { g_negv[i] = 0.0f; g_negt[i] = 0.0f; }
}

// ---------------------------------------------------------------------------
// K1: L2 normalize. grid = (B, 2); y=0 -> vision, y=1 -> text. 128 threads.
// ---------------------------------------------------------------------------
__global__ void k_norm(const float* __restrict__ V, const float* __restrict__ T, int D) {
    int row = blockIdx.x;
    const float* src = (blockIdx.y == 0) ? V : T;
    float*       dst = (blockIdx.y == 0) ? g_Vn : g_Tn;
    int tid = threadIdx.x;
    float ss = 0.0f;
    for (int idx = tid * 4; idx < D; idx += 128 * 4) {
        float4 v = *(const float4*)(src + (size_t)row * D + idx);
        ss += v.x * v.x + v.y * v.y + v.z * v.z + v.w * v.w;
    }
    #pragma unroll
    for (int o = 16; o > 0; o >>= 1) ss += __shfl_down_sync(0xffffffffu, ss, o);
    __shared__ float s[4];
    if ((tid & 31) == 0) s[tid >> 5] = ss;
    __syncthreads();
    float tot = s[0] + s[1] + s[2] + s[3];
    float scale = 1.0f / fmaxf(sqrtf(tot), 1e-12f);
    for (int idx = tid * 4; idx < D; idx += 128 * 4) {
        float4 v = *(const float4*)(src + (size_t)row * D + idx);
        v.x *= scale; v.y *= scale; v.z *= scale; v.w *= scale;
        *(float4*)(dst + (size_t)row * D + idx) = v;
    }
}

// ---------------------------------------------------------------------------
// K2: per-row positive means. One block per row i, 128 threads / 4 warps.
// Phase A: scan ids, collect matching j into a shared list.
// Phase B: warp-cooperative dot products: dv = v_i . t_j, dt = t_i . v_j.
// ---------------------------------------------------------------------------
__global__ void k_pos(int B, int D) {
    int i = blockIdx.x;
    int tid = threadIdx.x;
    __shared__ int   s_cnt;
    __shared__ int   s_list[MAXM];
    __shared__ float s_sv, s_st;
    if (tid == 0) { s_cnt = 0; s_sv = 0.0f; s_st = 0.0f; }
    __syncthreads();
    int my = g_mid[i];
    for (int j = tid; j < B; j += 128) {
        if (g_mid[j] == my) {
            int p = atomicAdd(&s_cnt, 1);
            if (p < MAXM) s_list[p] = j;
        }
    }
    __syncthreads();
    int cnt = min(s_cnt, MAXM);
    int warp = tid >> 5, lane = tid & 31;
    const float* vi = g_Vn + (size_t)i * D;
    const float* ti = g_Tn + (size_t)i * D;
    for (int m = warp; m < cnt; m += 4) {
        int j = s_list[m];
        const float* tj = g_Tn + (size_t)j * D;
        const float* vj = g_Vn + (size_t)j * D;
        float dv = 0.0f, dt = 0.0f;
        for (int idx = lane * 4; idx < D; idx += 128) {
            float4 a = *(const float4*)(vi + idx), b = *(const float4*)(tj + idx);
            dv += a.x * b.x + a.y * b.y + a.z * b.z + a.w * b.w;
            float4 c = *(const float4*)(ti + idx), d = *(const float4*)(vj + idx);
            dt += c.x * d.x + c.y * d.y + c.z * d.z + c.w * d.w;
        }
        #pragma unroll
        for (int o = 16; o > 0; o >>= 1) {
            dv += __shfl_down_sync(0xffffffffu, dv, o);
            dt += __shfl_down_sync(0xffffffffu, dt, o);
        }
        if (lane == 0) { atomicAdd(&s_sv, dv); atomicAdd(&s_st, dt); }
    }
    __syncthreads();
    if (tid == 0) {
        float c = (float)max(s_cnt, 1);
        g_mpv[i] = s_sv / c;
        g_mpt[i] = s_st / c;
        atomicAdd(&g_npos, s_cnt);
    }
}

// ---------------------------------------------------------------------------
// K3: fused sim GEMM + exp epilogue. 128x128 tile per CTA, 256 threads,
// 8x8 per-thread microtile, Kc=16. Epilogue accumulates weighted exp sums
// into per-row (v2t) and per-col (t2v) accumulators via shared atomics,
// then one global atomic per row/col per CTA.
// ---------------------------------------------------------------------------
__global__ void __launch_bounds__(256)
k_sim(int B, int D) {
    __shared__ float As[16][132];
    __shared__ float Bs[16][132];
    __shared__ int   s_midr[128], s_midc[128];
    __shared__ float s_mpv[128], s_mpt[128];
    __shared__ float s_nr[128], s_nc[128];

    int i0 = blockIdx.y * 128, j0 = blockIdx.x * 128;
    int tid = threadIdx.x;
    if (tid < 128) {
        s_midr[tid] = g_mid[i0 + tid];
        s_midc[tid] = g_mid[j0 + tid];
        s_mpv[tid]  = g_mpv[i0 + tid];
        s_mpt[tid]  = g_mpt[j0 + tid];
        s_nr[tid] = 0.0f; s_nc[tid] = 0.0f;
    }

    int lr = tid >> 1;            // 0..127, load row within tile
    int lc = (tid & 1) * 8;       // 0 or 8, k-offset of the 8 floats loaded
    int ty = tid >> 4, tx = tid & 15;

    float acc[8][8];
    #pragma unroll
    for (int r = 0; r < 8; r++)
        #pragma unroll
        for (int c = 0; c < 8; c++) acc[r][c] = 0.0f;

    for (int kt = 0; kt < D; kt += 16) {
        const float* pa = g_Vn + (size_t)(i0 + lr) * D + kt + lc;
        float4 a0 = *(const float4*)pa, a1 = *(const float4*)(pa + 4);
        const float* pb = g_Tn + (size_t)(j0 + lr) * D + kt + lc;
        float4 b0 = *(const float4*)pb, b1 = *(const float4*)(pb + 4);
        __syncthreads();   // previous iter compute done (and shared init, iter 0)
        As[lc + 0][lr] = a0.x; As[lc + 1][lr] = a0.y; As[lc + 2][lr] = a0.z; As[lc + 3][lr] = a0.w;
        As[lc + 4][lr] = a1.x; As[lc + 5][lr] = a1.y; As[lc + 6][lr] = a1.z; As[lc + 7][lr] = a1.w;
        Bs[lc + 0][lr] = b0.x; Bs[lc + 1][lr] = b0.y; Bs[lc + 2][lr] = b0.z; Bs[lc + 3][lr] = b0.w;
        Bs[lc + 4][lr] = b1.x; Bs[lc + 5][lr] = b1.y; Bs[lc + 6][lr] = b1.z; Bs[lc + 7][lr] = b1.w;
        __syncthreads();
        #pragma unroll
        for (int k = 0; k < 16; k++) {
            float4 fa0 = *(const float4*)&As[k][ty * 8];
            float4 fa1 = *(const float4*)&As[k][ty * 8 + 4];
            float4 fb0 = *(const float4*)&Bs[k][tx * 8];
            float4 fb1 = *(const float4*)&Bs[k][tx * 8 + 4];
            float ar[8] = {fa0.x, fa0.y, fa0.z, fa0.w, fa1.x, fa1.y, fa1.z, fa1.w};
            float br[8] = {fb0.x, fb0.y, fb0.z, fb0.w, fb1.x, fb1.y, fb1.z, fb1.w};
            #pragma unroll
            for (int r = 0; r < 8; r++)
                #pragma unroll
                for (int c = 0; c < 8; c++)
                    acc[r][c] = fmaf(ar[r], br[c], acc[r][c]);
        }
    }

    // Epilogue
    int   midr[8], midc[8];
    float mpvr[8], mptc[8];
    #pragma unroll
    for (int r = 0; r < 8; r++) { midr[r] = s_midr[ty * 8 + r]; mpvr[r] = s_mpv[ty * 8 + r]; }
    #pragma unroll
    for (int c = 0; c < 8; c++) { midc[c] = s_midc[tx * 8 + c]; mptc[c] = s_mpt[tx * 8 + c]; }

    float rs[8] = {0,0,0,0,0,0,0,0};
    float cs[8] = {0,0,0,0,0,0,0,0};
    #pragma unroll
    for (int r = 0; r < 8; r++) {
        #pragma unroll
        for (int c = 0; c < 8; c++) {
            float s = acc[r][c];
            float e = __expf(s * c_INV_T);
            if (midr[r] != midc[c]) {
                float wv = (s < mpvr[r] && s > mpvr[r] - c_MARGIN) ? 2.0f : 1.0f;
                float wt = (s < mptc[c] && s > mptc[c] - c_MARGIN) ? 2.0f : 1.0f;
                rs[r] += e * wv;
                cs[c] += e * wt;
            }
        }
    }
    #pragma unroll
    for (int r = 0; r < 8; r++) atomicAdd(&s_nr[ty * 8 + r], rs[r]);
    #pragma unroll
    for (int c = 0; c < 8; c++) atomicAdd(&s_nc[tx * 8 + c], cs[c]);
    __syncthreads();
    if (tid < 128) {
        atomicAdd(&g_negv[i0 + tid], s_nr[tid]);
        atomicAdd(&g_negt[j0 + tid], s_nc[tid]);
    }
}

// ---------------------------------------------------------------------------
// K4: finalize. One block per anchor i: recompute positive dots, add
// log1p(neg * exp(-sim_pos / T)) for both directions.
// ---------------------------------------------------------------------------
__global__ void k_final(int B, int D) {
    int i = blockIdx.x;
    int tid = threadIdx.x;
    __shared__ int   s_cnt;
    __shared__ int   s_list[MAXM];
    __shared__ float s_sum;
    if (tid == 0) { s_cnt = 0; s_sum = 0.0f; }
    __syncthreads();
    int my = g_mid[i];
    for (int j = tid; j < B; j += 128) {
        if (g_mid[j] == my) {
            int p = atomicAdd(&s_cnt, 1);
            if (p < MAXM) s_list[p] = j;
        }
    }
    __syncthreads();
    int cnt_full = s_cnt;
    int cnt = min(cnt_full, MAXM);
    // valid_row: pos_cnt > 0 && any not_match
    if (cnt_full == 0 || cnt_full >= B) return;

    int warp = tid >> 5, lane = tid & 31;
    const float* vi = g_Vn + (size_t)i * D;
    const float* ti = g_Tn + (size_t)i * D;
    float nv = g_negv[i];
    float nt = g_negt[i];
    for (int m = warp; m < cnt; m += 4) {
        int j = s_list[m];
        const float* tj = g_Tn + (size_t)j * D;
        const float* vj = g_Vn + (size_t)j * D;
        float dv = 0.0f, dt = 0.0f;
        for (int idx = lane * 4; idx < D; idx += 128) {
            float4 a = *(const float4*)(vi + idx), b = *(const float4*)(tj + idx);
            dv += a.x * b.x + a.y * b.y + a.z * b.z + a.w * b.w;
            float4 c = *(const float4*)(ti + idx), d = *(const float4*)(vj + idx);
            dt += c.x * d.x + c.y * d.y + c.z * d.z + c.w * d.w;
        }
        #pragma unroll
        for (int o = 16; o > 0; o >>= 1) {
            dv += __shfl_down_sync(0xffffffffu, dv, o);
            dt += __shfl_down_sync(0xffffffffu, dt, o);
        }
        if (lane == 0) {
            float term = log1pf(nv * __expf(-dv * c_INV_T))
                       + log1pf(nt * __expf(-dt * c_INV_T));
            atomicAdd(&s_sum, term);
        }
    }
    __syncthreads();
    if (tid == 0) atomicAdd(&g_loss, s_sum);
}

__global__ void k_out(float* out) {
    if (threadIdx.x == 0) {
        float np = (float)g_npos;
        out[0] = (g_npos > 0) ? g_loss / (2.0f * fmaxf(np, 1.0f)) : 0.0f;
    }
}

// ---------------------------------------------------------------------------
extern "C" void kernel_launch(void* const* d_in, const int* in_sizes, int n_in,
                              void* d_out, int out_size) {
    const float* V = (const float*)d_in[0];
    const float* T = (const float*)d_in[1];
    const unsigned int* ids = (const unsigned int*)d_in[2];
    int B = in_sizes[2];
    int D = in_sizes[0] / B;

    k_ids<<<1, 256>>>(ids, B);
    k_zero<<<(B + 255) / 256, 256>>>(B);
    dim3 gn(B, 2);
    k_norm<<<gn, 128>>>(V, T, D);
    k_pos<<<B, 128>>>(B, D);
    dim3 g3(B / 128, B / 128);
    k_sim<<<g3, 256>>>(B, D);
    k_final<<<B, 128>>>(B, D);
    k_out<<<1, 32>>>((float*)d_out);
}

// round 3
// speedup vs baseline: 1.9833x; 1.9833x over previous
#include <cuda_runtime.h>
#include <cuda_bf16.h>
#include <math.h>
#include <stdint.h>

#define B_MAX 4096
#define D_MAX 512
#define NB    2048
#define BCAP  32

__device__ float g_Vn[B_MAX * D_MAX];
__device__ float g_Tn[B_MAX * D_MAX];
__device__ __nv_bfloat16 g_Vh[B_MAX * D_MAX];
__device__ __nv_bfloat16 g_Vl[B_MAX * D_MAX];
__device__ __nv_bfloat16 g_Th[B_MAX * D_MAX];
__device__ __nv_bfloat16 g_Tl[B_MAX * D_MAX];
__device__ int   g_mid[B_MAX];
__device__ float g_mpv[B_MAX];
__device__ float g_mpt[B_MAX];
__device__ float g_negv[B_MAX];
__device__ float g_negt[B_MAX];
__device__ int   g_bcnt[NB];
__device__ int   g_blist[NB * BCAP];
__device__ float g_loss;
__device__ int   g_npos;

__constant__ float c_INV_T  = 1.0f / 0.07f;
__constant__ float c_MARGIN = 0.2f;

// ---------------- PTX helpers (sm_80-compatible only) ----------------
__device__ __forceinline__ uint32_t smem_u32(const void* p) {
    uint32_t a;
    asm("{ .reg .u64 t; cvta.to.shared.u64 t, %1; cvt.u32.u64 %0, t; }" : "=r"(a) : "l"(p));
    return a;
}
#define CP_ASYNC16(sp, gp) \
    asm volatile("cp.async.cg.shared.global [%0], [%1], 16;" :: "r"(sp), "l"(gp))
#define CP_COMMIT() asm volatile("cp.async.commit_group;" ::: "memory")
#define CP_WAIT(n)  asm volatile("cp.async.wait_group %0;" :: "n"(n) : "memory")

#define LDSM_X4(r, addr) \
    asm volatile("ldmatrix.sync.aligned.m8n8.x4.shared.b16 {%0,%1,%2,%3}, [%4];" \
        : "=r"((r)[0]), "=r"((r)[1]), "=r"((r)[2]), "=r"((r)[3]) : "r"(addr))

#define MMA16816(d, a, b0, b1) \
    asm volatile("mma.sync.aligned.m16n8k16.row.col.f32.bf16.bf16.f32 " \
        "{%0,%1,%2,%3}, {%4,%5,%6,%7}, {%8,%9}, {%0,%1,%2,%3};" \
        : "+f"((d)[0]), "+f"((d)[1]), "+f"((d)[2]), "+f"((d)[3]) \
        : "r"((a)[0]), "r"((a)[1]), "r"((a)[2]), "r"((a)[3]), "r"(b0), "r"(b1))

// ---------------------------------------------------------------------------
// K0: id dtype detect + convert; build hash buckets; zero scalars.
// ---------------------------------------------------------------------------
__global__ void k_ids(const unsigned int* __restrict__ raw, int B) {
    __shared__ int s_is64;
    int tid = threadIdx.x;
    if (tid == 0) s_is64 = 1;
    __syncthreads();
    int nchk = min(B / 2, 128);
    for (int i = tid; i < nchk; i += blockDim.x)
        if (raw[2 * i + 1] != 0u) atomicExch(&s_is64, 0);
    __syncthreads();
    bool is64 = (s_is64 != 0);
    for (int i = tid; i < B; i += blockDim.x) {
        long long v = is64 ? ((const long long*)raw)[i] : (long long)((const int*)raw)[i];
        g_mid[i] = (int)v;
    }
    for (int i = tid; i < NB; i += blockDim.x) g_bcnt[i] = 0;
    if (tid == 0) { g_loss = 0.0f; g_npos = 0; }
    __syncthreads();
    for (int i = tid; i < B; i += blockDim.x) {
        int b = g_mid[i] & (NB - 1);
        int p = atomicAdd(&g_bcnt[b], 1);
        if (p < BCAP) g_blist[b * BCAP + p] = i;
    }
}

__global__ void k_zero(int B) {
    int i = blockIdx.x * blockDim.x + threadIdx.x;
    if (i < B) { g_negv[i] = 0.0f; g_negt[i] = 0.0f; }
}

// ---------------------------------------------------------------------------
// K1: L2 normalize + bf16 hi/lo split emit. grid (B, 2).
// ---------------------------------------------------------------------------
__global__ void k_norm(const float* __restrict__ V, const float* __restrict__ T, int D) {
    int row = blockIdx.x;
    const float* src = (blockIdx.y == 0) ? V : T;
    float*       dst = (blockIdx.y == 0) ? g_Vn : g_Tn;
    __nv_bfloat16* dh = (blockIdx.y == 0) ? g_Vh : g_Th;
    __nv_bfloat16* dl = (blockIdx.y == 0) ? g_Vl : g_Tl;
    int tid = threadIdx.x;
    float ss = 0.0f;
    for (int idx = tid * 4; idx < D; idx += 512) {
        float4 v = *(const float4*)(src + (size_t)row * D + idx);
        ss += v.x * v.x + v.y * v.y + v.z * v.z + v.w * v.w;
    }
    #pragma unroll
    for (int o = 16; o > 0; o >>= 1) ss += __shfl_xor_sync(0xffffffffu, ss, o);
    __shared__ float s[4];
    if ((tid & 31) == 0) s[tid >> 5] = ss;
    __syncthreads();
    float scale = 1.0f / fmaxf(sqrtf(s[0] + s[1] + s[2] + s[3]), 1e-12f);
    for (int idx = tid * 4; idx < D; idx += 512) {
        float4 v = *(const float4*)(src + (size_t)row * D + idx);
        v.x *= scale; v.y *= scale; v.z *= scale; v.w *= scale;
        *(float4*)(dst + (size_t)row * D + idx) = v;
        size_t o = (size_t)row * D + idx;
        float c[4] = {v.x, v.y, v.z, v.w};
        #pragma unroll
        for (int q = 0; q < 4; q++) {
            __nv_bfloat16 h = __float2bfloat16(c[q]);
            dh[o + q] = h;
            dl[o + q] = __float2bfloat16(c[q] - __bfloat162float(h));
        }
    }
}

// ---------------------------------------------------------------------------
// K2: positive means via buckets. One warp per anchor row.
// ---------------------------------------------------------------------------
__global__ void k_pos(int B, int D) {
    int i = (blockIdx.x * blockDim.x + threadIdx.x) >> 5;
    if (i >= B) return;
    int lane = threadIdx.x & 31;
    int my = g_mid[i];
    int b = my & (NB - 1);
    int bc = g_bcnt[b];
    const float* vi = g_Vn + (size_t)i * D;
    const float* ti = g_Tn + (size_t)i * D;
    float sv = 0.0f, st = 0.0f;
    int cnt = 0;
    for (int m = 0; m < ((bc <= BCAP) ? bc : B); m++) {
        int j = (bc <= BCAP) ? g_blist[b * BCAP + m] : m;
        if (g_mid[j] != my) continue;
        cnt++;
        const float* tj = g_Tn + (size_t)j * D;
        const float* vj = g_Vn + (size_t)j * D;
        float dv = 0.0f, dt = 0.0f;
        for (int idx = lane * 4; idx < D; idx += 128) {
            float4 a = *(const float4*)(vi + idx), bb = *(const float4*)(tj + idx);
            dv += a.x * bb.x + a.y * bb.y + a.z * bb.z + a.w * bb.w;
            float4 c = *(const float4*)(ti + idx), d = *(const float4*)(vj + idx);
            dt += c.x * d.x + c.y * d.y + c.z * d.z + c.w * d.w;
        }
        #pragma unroll
        for (int o = 16; o > 0; o >>= 1) {
            dv += __shfl_xor_sync(0xffffffffu, dv, o);
            dt += __shfl_xor_sync(0xffffffffu, dt, o);
        }
        sv += dv; st += dt;
    }
    if (lane == 0) {
        float c = (float)max(cnt, 1);
        g_mpv[i] = sv / c;
        g_mpt[i] = st / c;
        atomicAdd(&g_npos, cnt);
    }
}

// ---------------------------------------------------------------------------
// K3: mma.sync bf16 GEMM, 3-term split, 128x128 tile, double-buffered cp.async.
// smem per stage: Ah, Al, Bh, Bl each [128 rows][40 bf16] (80B stride).
// ---------------------------------------------------------------------------
#define STG_BYTES 40960
#define T_AH 0
#define T_AL 10240
#define T_BH 20480
#define T_BL 30720

__global__ void __launch_bounds__(256) k_sim_mma(int B, int D) {
    extern __shared__ char dsm[];
    __shared__ int   s_midr[128], s_midc[128];
    __shared__ float s_mpv[128], s_mpt[128], s_nr[128], s_nc[128];

    int tid = threadIdx.x;
    int lane = tid & 31, wid = tid >> 5;
    int warpM = wid >> 1, warpN = wid & 1;
    int i0 = blockIdx.y * 128, j0 = blockIdx.x * 128;

    if (tid < 128) {
        s_midr[tid] = g_mid[i0 + tid];
        s_midc[tid] = g_mid[j0 + tid];
        s_mpv[tid]  = g_mpv[i0 + tid];
        s_mpt[tid]  = g_mpt[j0 + tid];
        s_nr[tid] = 0.0f; s_nc[tid] = 0.0f;
    }

    uint32_t sbase = smem_u32(dsm);

    float acc[2][8][4];
    #pragma unroll
    for (int mt = 0; mt < 2; mt++)
        #pragma unroll
        for (int nt = 0; nt < 8; nt++)
            #pragma unroll
            for (int e = 0; e < 4; e++) acc[mt][nt][e] = 0.0f;

    int nk = D >> 5;

#define LOAD_STAGE(st, kc)                                                      \
    {                                                                           \
        _Pragma("unroll")                                                       \
        for (int c = tid; c < 512; c += 256) {                                  \
            int row = c >> 2, seg = c & 3;                                      \
            int col = (kc) * 32 + seg * 8;                                      \
            uint32_t so = (uint32_t)(row * 80 + seg * 16);                      \
            CP_ASYNC16((st) + T_AH + so, g_Vh + (size_t)(i0 + row) * D + col);  \
            CP_ASYNC16((st) + T_AL + so, g_Vl + (size_t)(i0 + row) * D + col);  \
            CP_ASYNC16((st) + T_BH + so, g_Th + (size_t)(j0 + row) * D + col);  \
            CP_ASYNC16((st) + T_BL + so, g_Tl + (size_t)(j0 + row) * D + col);  \
        }                                                                       \
        CP_COMMIT();                                                            \
    }

    LOAD_STAGE(sbase, 0)

    for (int k = 0; k < nk; k++) {
        int buf = k & 1;
        if (k + 1 < nk) {
            LOAD_STAGE(sbase + (1 - buf) * STG_BYTES, k + 1)
            CP_WAIT(1);
        } else {
            CP_WAIT(0);
        }
        __syncthreads();

        uint32_t stg = sbase + buf * STG_BYTES;
        #pragma unroll
        for (int k16 = 0; k16 < 2; k16++) {
            uint32_t acol = (uint32_t)(k16 * 32 + (lane >> 4) * 16);
            uint32_t arow = (uint32_t)(warpM * 32 + (lane & 15));
            uint32_t brow = (uint32_t)(warpN * 64 + (lane & 15));
            uint32_t aoff = arow * 80 + acol;
            uint32_t boff = brow * 80 + acol;

            uint32_t bh[4][4];
            #pragma unroll
            for (int p = 0; p < 4; p++) LDSM_X4(bh[p], stg + T_BH + boff + p * 16 * 80);

            uint32_t ah[2][4];
            LDSM_X4(ah[0], stg + T_AH + aoff);
            LDSM_X4(ah[1], stg + T_AH + aoff + 16 * 80);

            // hi * hi
            #pragma unroll
            for (int mt = 0; mt < 2; mt++)
                #pragma unroll
                for (int p = 0; p < 4; p++) {
                    MMA16816(acc[mt][2 * p],     ah[mt], bh[p][0], bh[p][2]);
                    MMA16816(acc[mt][2 * p + 1], ah[mt], bh[p][1], bh[p][3]);
                }

            // lo * hi
            uint32_t al[2][4];
            LDSM_X4(al[0], stg + T_AL + aoff);
            LDSM_X4(al[1], stg + T_AL + aoff + 16 * 80);
            #pragma unroll
            for (int mt = 0; mt < 2; mt++)
                #pragma unroll
                for (int p = 0; p < 4; p++) {
                    MMA16816(acc[mt][2 * p],     al[mt], bh[p][0], bh[p][2]);
                    MMA16816(acc[mt][2 * p + 1], al[mt], bh[p][1], bh[p][3]);
                }

            // hi * lo
            uint32_t bl[4][4];
            #pragma unroll
            for (int p = 0; p < 4; p++) LDSM_X4(bl[p], stg + T_BL + boff + p * 16 * 80);
            #pragma unroll
            for (int mt = 0; mt < 2; mt++)
                #pragma unroll
                for (int p = 0; p < 4; p++) {
                    MMA16816(acc[mt][2 * p],     ah[mt], bl[p][0], bl[p][2]);
                    MMA16816(acc[mt][2 * p + 1], ah[mt], bl[p][1], bl[p][3]);
                }
        }
        __syncthreads();
    }

    // ---- epilogue ----
    int g = lane >> 2, tg = lane & 3;
    float rsum[2][2] = {{0.0f, 0.0f}, {0.0f, 0.0f}};
    float csum[8][2] = {};
    #pragma unroll
    for (int mt = 0; mt < 2; mt++) {
        int r0 = warpM * 32 + mt * 16 + g;
        int r1 = r0 + 8;
        int mid0 = s_midr[r0], mid1 = s_midr[r1];
        float mp0 = s_mpv[r0], mp1 = s_mpv[r1];
        #pragma unroll
        for (int nt = 0; nt < 8; nt++) {
            #pragma unroll
            for (int e = 0; e < 2; e++) {
                int cidx = warpN * 64 + nt * 8 + tg * 2 + e;
                int midc = s_midc[cidx];
                float mpt = s_mpt[cidx];
                float sv0 = acc[mt][nt][e];
                float sv1 = acc[mt][nt][e + 2];
                float e0 = __expf(sv0 * c_INV_T);
                float e1 = __expf(sv1 * c_INV_T);
                if (mid0 != midc) {
                    float w = (sv0 < mp0 && sv0 > mp0 - c_MARGIN) ? 2.0f : 1.0f;
                    float wc = (sv0 < mpt && sv0 > mpt - c_MARGIN) ? 2.0f : 1.0f;
                    rsum[mt][0] += e0 * w;
                    csum[nt][e] += e0 * wc;
                }
                if (mid1 != midc) {
                    float w = (sv1 < mp1 && sv1 > mp1 - c_MARGIN) ? 2.0f : 1.0f;
                    float wc = (sv1 < mpt && sv1 > mpt - c_MARGIN) ? 2.0f : 1.0f;
                    rsum[mt][1] += e1 * w;
                    csum[nt][e] += e1 * wc;
                }
            }
        }
    }
    // row reduce across quad (tg) lanes
    #pragma unroll
    for (int o = 1; o <= 2; o <<= 1) {
        #pragma unroll
        for (int mt = 0; mt < 2; mt++) {
            rsum[mt][0] += __shfl_xor_sync(0xffffffffu, rsum[mt][0], o);
            rsum[mt][1] += __shfl_xor_sync(0xffffffffu, rsum[mt][1], o);
        }
    }
    if (tg == 0) {
        #pragma unroll
        for (int mt = 0; mt < 2; mt++) {
            atomicAdd(&s_nr[warpM * 32 + mt * 16 + g],     rsum[mt][0]);
            atomicAdd(&s_nr[warpM * 32 + mt * 16 + g + 8], rsum[mt][1]);
        }
    }
    // col reduce across group (g) lanes
    #pragma unroll
    for (int o = 4; o <= 16; o <<= 1)
        #pragma unroll
        for (int nt = 0; nt < 8; nt++) {
            csum[nt][0] += __shfl_xor_sync(0xffffffffu, csum[nt][0], o);
            csum[nt][1] += __shfl_xor_sync(0xffffffffu, csum[nt][1], o);
        }
    if (g == 0) {
        #pragma unroll
        for (int nt = 0; nt < 8; nt++) {
            atomicAdd(&s_nc[warpN * 64 + nt * 8 + tg * 2],     csum[nt][0]);
            atomicAdd(&s_nc[warpN * 64 + nt * 8 + tg * 2 + 1], csum[nt][1]);
        }
    }
    __syncthreads();
    if (tid < 128) {
        atomicAdd(&g_negv[i0 + tid], s_nr[tid]);
        atomicAdd(&g_negt[j0 + tid], s_nc[tid]);
    }
}

// ---------------------------------------------------------------------------
// K3 fallback (SIMT 128x128) for odd shapes.
// ---------------------------------------------------------------------------
__global__ void __launch_bounds__(256) k_sim_simt(int B, int D) {
    __shared__ float As[16][132];
    __shared__ float Bs[16][132];
    __shared__ int   s_midr[128], s_midc[128];
    __shared__ float s_mpv[128], s_mpt[128];
    __shared__ float s_nr[128], s_nc[128];

    int i0 = blockIdx.y * 128, j0 = blockIdx.x * 128;
    int tid = threadIdx.x;
    if (tid < 128) {
        s_midr[tid] = g_mid[i0 + tid];
        s_midc[tid] = g_mid[j0 + tid];
        s_mpv[tid]  = g_mpv[i0 + tid];
        s_mpt[tid]  = g_mpt[j0 + tid];
        s_nr[tid] = 0.0f; s_nc[tid] = 0.0f;
    }
    int lr = tid >> 1, lc = (tid & 1) * 8;
    int ty = tid >> 4, tx = tid & 15;
    float acc[8][8];
    #pragma unroll
    for (int r = 0; r < 8; r++)
        #pragma unroll
        for (int c = 0; c < 8; c++) acc[r][c] = 0.0f;
    for (int kt = 0; kt < D; kt += 16) {
        const float* pa = g_Vn + (size_t)(i0 + lr) * D + kt + lc;
        float4 a0 = *(const float4*)pa, a1 = *(const float4*)(pa + 4);
        const float* pb = g_Tn + (size_t)(j0 + lr) * D + kt + lc;
        float4 b0 = *(const float4*)pb, b1 = *(const float4*)(pb + 4);
        __syncthreads();
        As[lc+0][lr]=a0.x; As[lc+1][lr]=a0.y; As[lc+2][lr]=a0.z; As[lc+3][lr]=a0.w;
        As[lc+4][lr]=a1.x; As[lc+5][lr]=a1.y; As[lc+6][lr]=a1.z; As[lc+7][lr]=a1.w;
        Bs[lc+0][lr]=b0.x; Bs[lc+1][lr]=b0.y; Bs[lc+2][lr]=b0.z; Bs[lc+3][lr]=b0.w;
        Bs[lc+4][lr]=b1.x; Bs[lc+5][lr]=b1.y; Bs[lc+6][lr]=b1.z; Bs[lc+7][lr]=b1.w;
        __syncthreads();
        #pragma unroll
        for (int k = 0; k < 16; k++) {
            float4 fa0 = *(const float4*)&As[k][ty*8], fa1 = *(const float4*)&As[k][ty*8+4];
            float4 fb0 = *(const float4*)&Bs[k][tx*8], fb1 = *(const float4*)&Bs[k][tx*8+4];
            float ar[8] = {fa0.x,fa0.y,fa0.z,fa0.w,fa1.x,fa1.y,fa1.z,fa1.w};
            float br[8] = {fb0.x,fb0.y,fb0.z,fb0.w,fb1.x,fb1.y,fb1.z,fb1.w};
            #pragma unroll
            for (int r = 0; r < 8; r++)
                #pragma unroll
                for (int c = 0; c < 8; c++)
                    acc[r][c] = fmaf(ar[r], br[c], acc[r][c]);
        }
    }
    int midr[8], midc[8]; float mpvr[8], mptc[8];
    #pragma unroll
    for (int r = 0; r < 8; r++) { midr[r]=s_midr[ty*8+r]; mpvr[r]=s_mpv[ty*8+r]; }
    #pragma unroll
    for (int c = 0; c < 8; c++) { midc[c]=s_midc[tx*8+c]; mptc[c]=s_mpt[tx*8+c]; }
    float rs[8] = {0,0,0,0,0,0,0,0}, cs[8] = {0,0,0,0,0,0,0,0};
    #pragma unroll
    for (int r = 0; r < 8; r++)
        #pragma unroll
        for (int c = 0; c < 8; c++) {
            float sv = acc[r][c];
            float e = __expf(sv * c_INV_T);
            if (midr[r] != midc[c]) {
                rs[r] += e * ((sv < mpvr[r] && sv > mpvr[r] - c_MARGIN) ? 2.0f : 1.0f);
                cs[c] += e * ((sv < mptc[c] && sv > mptc[c] - c_MARGIN) ? 2.0f : 1.0f);
            }
        }
    #pragma unroll
    for (int r = 0; r < 8; r++) atomicAdd(&s_nr[ty*8+r], rs[r]);
    #pragma unroll
    for (int c = 0; c < 8; c++) atomicAdd(&s_nc[tx*8+c], cs[c]);
    __syncthreads();
    if (tid < 128) {
        atomicAdd(&g_negv[i0 + tid], s_nr[tid]);
        atomicAdd(&g_negt[j0 + tid], s_nc[tid]);
    }
}

// ---------------------------------------------------------------------------
// K4: finalize per anchor (one warp per row, bucketed).
// ---------------------------------------------------------------------------
__global__ void k_final(int B, int D) {
    int i = (blockIdx.x * blockDim.x + threadIdx.x) >> 5;
    if (i >= B) return;
    int lane = threadIdx.x & 31;
    int my = g_mid[i];
    int b = my & (NB - 1);
    int bc = g_bcnt[b];
    const float* vi = g_Vn + (size_t)i * D;
    const float* ti = g_Tn + (size_t)i * D;
    float nv = g_negv[i], nt = g_negt[i];
    float ts = 0.0f;
    int cnt = 0;
    for (int m = 0; m < ((bc <= BCAP) ? bc : B); m++) {
        int j = (bc <= BCAP) ? g_blist[b * BCAP + m] : m;
        if (g_mid[j] != my) continue;
        cnt++;
        const float* tj = g_Tn + (size_t)j * D;
        const float* vj = g_Vn + (size_t)j * D;
        float dv = 0.0f, dt = 0.0f;
        for (int idx = lane * 4; idx < D; idx += 128) {
            float4 a = *(const float4*)(vi + idx), bb = *(const float4*)(tj + idx);
            dv += a.x * bb.x + a.y * bb.y + a.z * bb.z + a.w * bb.w;
            float4 c = *(const float4*)(ti + idx), d = *(const float4*)(vj + idx);
            dt += c.x * d.x + c.y * d.y + c.z * d.z + c.w * d.w;
        }
        #pragma unroll
        for (int o = 16; o > 0; o >>= 1) {
            dv += __shfl_xor_sync(0xffffffffu, dv, o);
            dt += __shfl_xor_sync(0xffffffffu, dt, o);
        }
        ts += log1pf(nv * __expf(-dv * c_INV_T)) + log1pf(nt * __expf(-dt * c_INV_T));
    }
    if (lane == 0 && cnt > 0 && cnt < B) atomicAdd(&g_loss, ts);
}

__global__ void k_out(float* out) {
    if (threadIdx.x == 0) {
        float np = (float)g_npos;
        out[0] = (g_npos > 0) ? g_loss / (2.0f * fmaxf(np, 1.0f)) : 0.0f;
    }
}

// ---------------------------------------------------------------------------
extern "C" void kernel_launch(void* const* d_in, const int* in_sizes, int n_in,
                              void* d_out, int out_size) {
    const float* V = (const float*)d_in[0];
    const float* T = (const float*)d_in[1];
    const unsigned int* ids = (const unsigned int*)d_in[2];
    int B = in_sizes[2];
    int D = in_sizes[0] / B;

    k_ids<<<1, 256>>>(ids, B);
    k_zero<<<(B + 255) / 256, 256>>>(B);
    dim3 gn(B, 2);
    k_norm<<<gn, 128>>>(V, T, D);
    k_pos<<<(B + 7) / 8, 256>>>(B, D);

    bool tc_ok = (B % 128 == 0) && (D % 32 == 0) && (D >= 32) &&
                 (B <= B_MAX) && (D <= D_MAX);
    if (tc_ok) {
        const int DYN = 2 * STG_BYTES;  // 81920
        cudaFuncSetAttribute(k_sim_mma, cudaFuncAttributeMaxDynamicSharedMemorySize, DYN);
        dim3 g3(B / 128, B / 128);
        k_sim_mma<<<g3, 256, DYN>>>(B, D);
    } else {
        dim3 g3((B + 127) / 128, (B + 127) / 128);
        k_sim_simt<<<g3, 256>>>(B, D);
    }
    k_final<<<(B + 7) / 8, 256>>>(B, D);
    k_out<<<1, 32>>>((float*)d_out);
}

// round 4
// speedup vs baseline: 2.5826x; 1.3021x over previous
#include <cuda_runtime.h>
#include <cuda_bf16.h>
#include <math.h>
#include <stdint.h>

#define B_MAX 4096
#define D_MAX 512
#define NB    2048
#define BCAP  32
#define NPAIR_MAX 262144
#define ROWCAP 64

__device__ float g_Vn[B_MAX * D_MAX];
__device__ float g_Tn[B_MAX * D_MAX];
__device__ char  g_Vq1[B_MAX * D_MAX];
__device__ char  g_Vq2[B_MAX * D_MAX];
__device__ char  g_Tq1[B_MAX * D_MAX];
__device__ char  g_Tq2[B_MAX * D_MAX];
__device__ float g_sV[B_MAX];
__device__ float g_sT[B_MAX];
__device__ int   g_mid[B_MAX];
__device__ float g_mpv[B_MAX];
__device__ float g_mpt[B_MAX];
__device__ float g_negv[B_MAX];
__device__ float g_negt[B_MAX];
__device__ float g_sumv[B_MAX];
__device__ float g_sumt[B_MAX];
__device__ int   g_cnt[B_MAX];
__device__ int   g_slow[B_MAX];
__device__ int   g_bcnt[NB];
__device__ int   g_blist[NB * BCAP];
__device__ int2  g_pairs[NPAIR_MAX];
__device__ float2 g_pd[NPAIR_MAX];
__device__ int   g_pcnt;
__device__ float g_loss;
__device__ int   g_npos;

__constant__ float c_INV_T  = 1.0f / 0.07f;
__constant__ float c_MARGIN = 0.2f;

// ---------------- PTX helpers (sm_80-compatible) ----------------
__device__ __forceinline__ uint32_t smem_u32(const void* p) {
    uint32_t a;
    asm("{ .reg .u64 t; cvta.to.shared.u64 t, %1; cvt.u32.u64 %0, t; }" : "=r"(a) : "l"(p));
    return a;
}
#define CP_ASYNC16(sp, gp) \
    asm volatile("cp.async.cg.shared.global [%0], [%1], 16;" :: "r"(sp), "l"(gp))
#define CP_COMMIT() asm volatile("cp.async.commit_group;" ::: "memory")
#define CP_WAIT(n)  asm volatile("cp.async.wait_group %0;" :: "n"(n) : "memory")

#define LDSM_X4(r, addr) \
    asm volatile("ldmatrix.sync.aligned.m8n8.x4.shared.b16 {%0,%1,%2,%3}, [%4];" \
        : "=r"((r)[0]), "=r"((r)[1]), "=r"((r)[2]), "=r"((r)[3]) : "r"(addr))

#define MMAS8(d, a, b0, b1) \
    asm volatile("mma.sync.aligned.m16n8k32.row.col.s32.s8.s8.s32 " \
        "{%0,%1,%2,%3}, {%4,%5,%6,%7}, {%8,%9}, {%0,%1,%2,%3};" \
        : "+r"((d)[0]), "+r"((d)[1]), "+r"((d)[2]), "+r"((d)[3]) \
        : "r"((a)[0]), "r"((a)[1]), "r"((a)[2]), "r"((a)[3]), "r"(b0), "r"(b1))

// ---------------------------------------------------------------------------
// K0: id detect/convert + buckets + zero scalars
// ---------------------------------------------------------------------------
__global__ void k_ids(const unsigned int* __restrict__ raw, int B) {
    __shared__ int s_is64;
    int tid = threadIdx.x;
    if (tid == 0) s_is64 = 1;
    __syncthreads();
    int nchk = min(B / 2, 128);
    for (int i = tid; i < nchk; i += blockDim.x)
        if (raw[2 * i + 1] != 0u) atomicExch(&s_is64, 0);
    __syncthreads();
    bool is64 = (s_is64 != 0);
    for (int i = tid; i < B; i += blockDim.x) {
        long long v = is64 ? ((const long long*)raw)[i] : (long long)((const int*)raw)[i];
        g_mid[i] = (int)v;
    }
    for (int i = tid; i < NB; i += blockDim.x) g_bcnt[i] = 0;
    if (tid == 0) { g_loss = 0.0f; g_npos = 0; g_pcnt = 0; }
    __syncthreads();
    for (int i = tid; i < B; i += blockDim.x) {
        int b = g_mid[i] & (NB - 1);
        int p = atomicAdd(&g_bcnt[b], 1);
        if (p < BCAP) g_blist[b * BCAP + p] = i;
    }
}

__global__ void k_zero(int B) {
    int i = blockIdx.x * blockDim.x + threadIdx.x;
    if (i < B) {
        g_negv[i] = 0.0f; g_negt[i] = 0.0f;
        g_sumv[i] = 0.0f; g_sumt[i] = 0.0f;
        g_slow[i] = 0;
    }
}

// ---------------------------------------------------------------------------
// K1: L2 normalize + two-level int8 quantize. grid (B, 2), 128 threads.
// ---------------------------------------------------------------------------
__global__ void k_norm(const float* __restrict__ V, const float* __restrict__ T, int D) {
    int row = blockIdx.x;
    const float* src = (blockIdx.y == 0) ? V : T;
    float* dst   = (blockIdx.y == 0) ? g_Vn : g_Tn;
    char*  dq1   = (blockIdx.y == 0) ? g_Vq1 : g_Tq1;
    char*  dq2   = (blockIdx.y == 0) ? g_Vq2 : g_Tq2;
    float* dsc   = (blockIdx.y == 0) ? g_sV : g_sT;
    int tid = threadIdx.x;
    __shared__ float s[4];

    float ss = 0.0f;
    for (int idx = tid * 4; idx < D; idx += 512) {
        float4 v = *(const float4*)(src + (size_t)row * D + idx);
        ss += v.x * v.x + v.y * v.y + v.z * v.z + v.w * v.w;
    }
    #pragma unroll
    for (int o = 16; o > 0; o >>= 1) ss += __shfl_xor_sync(0xffffffffu, ss, o);
    if ((tid & 31) == 0) s[tid >> 5] = ss;
    __syncthreads();
    float scale = 1.0f / fmaxf(sqrtf(s[0] + s[1] + s[2] + s[3]), 1e-12f);
    __syncthreads();

    // pass 2: write fp32, track amax
    float amax = 0.0f;
    for (int idx = tid * 4; idx < D; idx += 512) {
        float4 v = *(const float4*)(src + (size_t)row * D + idx);
        v.x *= scale; v.y *= scale; v.z *= scale; v.w *= scale;
        *(float4*)(dst + (size_t)row * D + idx) = v;
        amax = fmaxf(amax, fmaxf(fmaxf(fabsf(v.x), fabsf(v.y)), fmaxf(fabsf(v.z), fabsf(v.w))));
    }
    #pragma unroll
    for (int o = 16; o > 0; o >>= 1) amax = fmaxf(amax, __shfl_xor_sync(0xffffffffu, amax, o));
    if ((tid & 31) == 0) s[tid >> 5] = amax;
    __syncthreads();
    amax = fmaxf(fmaxf(s[0], s[1]), fmaxf(s[2], s[3]));
    float qs = fmaxf(amax / 127.0f, 1e-20f);
    float inv_qs = 1.0f / qs;
    if (tid == 0) dsc[row] = qs;

    // pass 3: quantize (reads dst, L1-hot)
    for (int idx = tid * 4; idx < D; idx += 512) {
        float4 v = *(const float4*)(dst + (size_t)row * D + idx);
        float c[4] = {v.x, v.y, v.z, v.w};
        char q1c[4], q2c[4];
        #pragma unroll
        for (int q = 0; q < 4; q++) {
            int q1 = __float2int_rn(c[q] * inv_qs);
            q1 = max(-127, min(127, q1));
            float r = c[q] - qs * (float)q1;
            int q2 = __float2int_rn(r * inv_qs * 128.0f);
            q2 = max(-127, min(127, q2));
            q1c[q] = (char)q1; q2c[q] = (char)q2;
        }
        *(char4*)(dq1 + (size_t)row * D + idx) = make_char4(q1c[0], q1c[1], q1c[2], q1c[3]);
        *(char4*)(dq2 + (size_t)row * D + idx) = make_char4(q2c[0], q2c[1], q2c[2], q2c[3]);
    }
}

// ---------------------------------------------------------------------------
// K2: build pair list
// ---------------------------------------------------------------------------
__global__ void k_pairs(int B) {
    int i = blockIdx.x * blockDim.x + threadIdx.x;
    if (i >= B) return;
    int my = g_mid[i];
    int b = my & (NB - 1);
    int bc = g_bcnt[b];
    int n = (bc <= BCAP) ? bc : B;
    int cnt = 0, stored = 0;
    bool slow = false;
    for (int m = 0; m < n; m++) {
        int j = (bc <= BCAP) ? g_blist[b * BCAP + m] : m;
        if (g_mid[j] != my) continue;
        cnt++;
        if (stored < ROWCAP) {
            int pos = atomicAdd(&g_pcnt, 1);
            if (pos < NPAIR_MAX) { g_pairs[pos] = make_int2(i, j); stored++; }
            else slow = true;
        } else slow = true;
    }
    g_cnt[i] = cnt;
    if (slow) g_slow[i] = 1;
    atomicAdd(&g_npos, cnt);
}

// ---------------------------------------------------------------------------
// K3: pair dots (warp per pair, grid-stride)
// ---------------------------------------------------------------------------
__global__ void k_pdots(int B, int D) {
    int np = min(g_pcnt, NPAIR_MAX);
    int w = (blockIdx.x * blockDim.x + threadIdx.x) >> 5;
    int lane = threadIdx.x & 31;
    int nw = (gridDim.x * blockDim.x) >> 5;
    for (int p = w; p < np; p += nw) {
        int2 pr = g_pairs[p];
        int i = pr.x, j = pr.y;
        const float* vi = g_Vn + (size_t)i * D;
        const float* ti = g_Tn + (size_t)i * D;
        const float* tj = g_Tn + (size_t)j * D;
        const float* vj = g_Vn + (size_t)j * D;
        float dv = 0.0f, dt = 0.0f;
        for (int idx = lane * 4; idx < D; idx += 128) {
            float4 a = *(const float4*)(vi + idx), bb = *(const float4*)(tj + idx);
            dv += a.x * bb.x + a.y * bb.y + a.z * bb.z + a.w * bb.w;
            float4 c = *(const float4*)(ti + idx), d = *(const float4*)(vj + idx);
            dt += c.x * d.x + c.y * d.y + c.z * d.z + c.w * d.w;
        }
        #pragma unroll
        for (int o = 16; o > 0; o >>= 1) {
            dv += __shfl_xor_sync(0xffffffffu, dv, o);
            dt += __shfl_xor_sync(0xffffffffu, dt, o);
        }
        if (lane == 0) {
            g_pd[p] = make_float2(dv, dt);
            if (!g_slow[i]) {
                atomicAdd(&g_sumv[i], dv);
                atomicAdd(&g_sumt[i], dt);
            }
        }
    }
}

__global__ void k_mean(int B) {
    int i = blockIdx.x * blockDim.x + threadIdx.x;
    if (i >= B || g_slow[i]) return;
    float c = (float)max(g_cnt[i], 1);
    g_mpv[i] = g_sumv[i] / c;
    g_mpt[i] = g_sumt[i] / c;
}

// slow path: full-scan mean for flagged rows (warp per row, early exit)
__global__ void k_pos_slow(int B, int D) {
    int i = (blockIdx.x * blockDim.x + threadIdx.x) >> 5;
    if (i >= B || !g_slow[i]) return;
    int lane = threadIdx.x & 31;
    int my = g_mid[i];
    const float* vi = g_Vn + (size_t)i * D;
    const float* ti = g_Tn + (size_t)i * D;
    float sv = 0.0f, st = 0.0f;
    for (int j = 0; j < B; j++) {
        if (g_mid[j] != my) continue;
        const float* tj = g_Tn + (size_t)j * D;
        const float* vj = g_Vn + (size_t)j * D;
        float dv = 0.0f, dt = 0.0f;
        for (int idx = lane * 4; idx < D; idx += 128) {
            float4 a = *(const float4*)(vi + idx), bb = *(const float4*)(tj + idx);
            dv += a.x * bb.x + a.y * bb.y + a.z * bb.z + a.w * bb.w;
            float4 c = *(const float4*)(ti + idx), d = *(const float4*)(vj + idx);
            dt += c.x * d.x + c.y * d.y + c.z * d.z + c.w * d.w;
        }
        sv += dv; st += dt;
    }
    #pragma unroll
    for (int o = 16; o > 0; o >>= 1) {
        sv += __shfl_xor_sync(0xffffffffu, sv, o);
        st += __shfl_xor_sync(0xffffffffu, st, o);
    }
    if (lane == 0) {
        float c = (float)max(g_cnt[i], 1);
        g_mpv[i] = sv / c;
        g_mpt[i] = st / c;
    }
}

// ---------------------------------------------------------------------------
// K4: int8 IMMA sim GEMM. 128x128 tile, 256 thr, k-chunk 64, double buffer.
// sim = sA_i*sB_j*(hh + cross/128)
// ---------------------------------------------------------------------------
#define ISTG 40960
#define T_AQ1 0
#define T_AQ2 10240
#define T_BQ1 20480
#define T_BQ2 30720

__global__ void __launch_bounds__(256, 1) k_sim_imma(int B, int D) {
    extern __shared__ char dsm[];
    __shared__ int   s_midr[128], s_midc[128];
    __shared__ float s_mpv[128], s_mpt[128], s_nr[128], s_nc[128];
    __shared__ float s_sa[128], s_sb[128];

    int tid = threadIdx.x;
    int lane = tid & 31, wid = tid >> 5;
    int warpM = wid >> 1, warpN = wid & 1;
    int i0 = blockIdx.y * 128, j0 = blockIdx.x * 128;

    if (tid < 128) {
        s_midr[tid] = g_mid[i0 + tid];
        s_midc[tid] = g_mid[j0 + tid];
        s_mpv[tid]  = g_mpv[i0 + tid];
        s_mpt[tid]  = g_mpt[j0 + tid];
        s_sa[tid]   = g_sV[i0 + tid];
        s_sb[tid]   = g_sT[j0 + tid];
        s_nr[tid] = 0.0f; s_nc[tid] = 0.0f;
    }

    uint32_t sbase = smem_u32(dsm);

    int acc_hh[2][8][4], acc_x[2][8][4];
    #pragma unroll
    for (int mt = 0; mt < 2; mt++)
        #pragma unroll
        for (int nt = 0; nt < 8; nt++)
            #pragma unroll
            for (int e = 0; e < 4; e++) { acc_hh[mt][nt][e] = 0; acc_x[mt][nt][e] = 0; }

    int nk = D >> 6;

#define ILOAD(st, kc)                                                            \
    {                                                                            \
        _Pragma("unroll")                                                        \
        for (int c = tid; c < 512; c += 256) {                                   \
            int row = c >> 2, seg = c & 3;                                       \
            int col = (kc) * 64 + seg * 16;                                      \
            uint32_t so = (uint32_t)(row * 80 + seg * 16);                       \
            CP_ASYNC16((st) + T_AQ1 + so, g_Vq1 + (size_t)(i0 + row) * D + col); \
            CP_ASYNC16((st) + T_AQ2 + so, g_Vq2 + (size_t)(i0 + row) * D + col); \
            CP_ASYNC16((st) + T_BQ1 + so, g_Tq1 + (size_t)(j0 + row) * D + col); \
            CP_ASYNC16((st) + T_BQ2 + so, g_Tq2 + (size_t)(j0 + row) * D + col); \
        }                                                                        \
        CP_COMMIT();                                                             \
    }

    ILOAD(sbase, 0)

    for (int k = 0; k < nk; k++) {
        int buf = k & 1;
        if (k + 1 < nk) { ILOAD(sbase + (1 - buf) * ISTG, k + 1) CP_WAIT(1); }
        else           { CP_WAIT(0); }
        __syncthreads();

        uint32_t stg = sbase + buf * ISTG;
        #pragma unroll
        for (int k32 = 0; k32 < 2; k32++) {
            uint32_t aq1[2][4], aq2[2][4];
            #pragma unroll
            for (int mt = 0; mt < 2; mt++) {
                uint32_t ao = stg + (uint32_t)((warpM * 32 + mt * 16 + (lane & 15)) * 80
                              + k32 * 32 + (lane >> 4) * 16);
                LDSM_X4(aq1[mt], ao + T_AQ1);
                LDSM_X4(aq2[mt], ao + T_AQ2);
            }
            #pragma unroll
            for (int p = 0; p < 4; p++) {
                uint32_t bo = stg + (uint32_t)((warpN * 64 + p * 16 + (lane & 7)
                              + ((lane >> 4) & 1) * 8) * 80
                              + ((lane >> 3) & 1) * 16 + k32 * 32);
                uint32_t b1f[4], b2f[4];
                LDSM_X4(b1f, bo + T_BQ1);
                LDSM_X4(b2f, bo + T_BQ2);
                #pragma unroll
                for (int mt = 0; mt < 2; mt++) {
                    MMAS8(acc_hh[mt][2 * p],     aq1[mt], b1f[0], b1f[1]);
                    MMAS8(acc_hh[mt][2 * p + 1], aq1[mt], b1f[2], b1f[3]);
                    MMAS8(acc_x[mt][2 * p],      aq1[mt], b2f[0], b2f[1]);
                    MMAS8(acc_x[mt][2 * p + 1],  aq1[mt], b2f[2], b2f[3]);
                    MMAS8(acc_x[mt][2 * p],      aq2[mt], b1f[0], b1f[1]);
                    MMAS8(acc_x[mt][2 * p + 1],  aq2[mt], b1f[2], b1f[3]);
                }
            }
        }
        __syncthreads();
    }

    // ---- epilogue ----
    int g = lane >> 2, tg = lane & 3;
    float rsum[2][2] = {{0.0f, 0.0f}, {0.0f, 0.0f}};
    float csum[8][2] = {};
    #pragma unroll
    for (int mt = 0; mt < 2; mt++) {
        int r0 = warpM * 32 + mt * 16 + g;
        int r1 = r0 + 8;
        int mid0 = s_midr[r0], mid1 = s_midr[r1];
        float mp0 = s_mpv[r0], mp1 = s_mpv[r1];
        float sa0 = s_sa[r0], sa1 = s_sa[r1];
        #pragma unroll
        for (int nt = 0; nt < 8; nt++) {
            #pragma unroll
            for (int e = 0; e < 2; e++) {
                int cidx = warpN * 64 + nt * 8 + tg * 2 + e;
                int midc = s_midc[cidx];
                float mpt = s_mpt[cidx];
                float sb = s_sb[cidx];
                float sv0 = ((float)acc_hh[mt][nt][e] + (float)acc_x[mt][nt][e] * 0.0078125f) * sa0 * sb;
                float sv1 = ((float)acc_hh[mt][nt][e + 2] + (float)acc_x[mt][nt][e + 2] * 0.0078125f) * sa1 * sb;
                float e0 = __expf(sv0 * c_INV_T);
                float e1 = __expf(sv1 * c_INV_T);
                if (mid0 != midc) {
                    float w = (sv0 < mp0 && sv0 > mp0 - c_MARGIN) ? 2.0f : 1.0f;
                    float wc = (sv0 < mpt && sv0 > mpt - c_MARGIN) ? 2.0f : 1.0f;
                    rsum[mt][0] += e0 * w;
                    csum[nt][e] += e0 * wc;
                }
                if (mid1 != midc) {
                    float w = (sv1 < mp1 && sv1 > mp1 - c_MARGIN) ? 2.0f : 1.0f;
                    float wc = (sv1 < mpt && sv1 > mpt - c_MARGIN) ? 2.0f : 1.0f;
                    rsum[mt][1] += e1 * w;
                    csum[nt][e] += e1 * wc;
                }
            }
        }
    }
    #pragma unroll
    for (int o = 1; o <= 2; o <<= 1) {
        #pragma unroll
        for (int mt = 0; mt < 2; mt++) {
            rsum[mt][0] += __shfl_xor_sync(0xffffffffu, rsum[mt][0], o);
            rsum[mt][1] += __shfl_xor_sync(0xffffffffu, rsum[mt][1], o);
        }
    }
    if (tg == 0) {
        #pragma unroll
        for (int mt = 0; mt < 2; mt++) {
            atomicAdd(&s_nr[warpM * 32 + mt * 16 + g],     rsum[mt][0]);
            atomicAdd(&s_nr[warpM * 32 + mt * 16 + g + 8], rsum[mt][1]);
        }
    }
    #pragma unroll
    for (int o = 4; o <= 16; o <<= 1)
        #pragma unroll
        for (int nt = 0; nt < 8; nt++) {
            csum[nt][0] += __shfl_xor_sync(0xffffffffu, csum[nt][0], o);
            csum[nt][1] += __shfl_xor_sync(0xffffffffu, csum[nt][1], o);
        }
    if (g == 0) {
        #pragma unroll
        for (int nt = 0; nt < 8; nt++) {
            atomicAdd(&s_nc[warpN * 64 + nt * 8 + tg * 2],     csum[nt][0]);
            atomicAdd(&s_nc[warpN * 64 + nt * 8 + tg * 2 + 1], csum[nt][1]);
        }
    }
    __syncthreads();
    if (tid < 128) {
        atomicAdd(&g_negv[i0 + tid], s_nr[tid]);
        atomicAdd(&g_negt[j0 + tid], s_nc[tid]);
    }
}

// ---------------------------------------------------------------------------
// SIMT fallback for odd shapes
// ---------------------------------------------------------------------------
__global__ void __launch_bounds__(256) k_sim_simt(int B, int D) {
    __shared__ float As[16][132];
    __shared__ float Bs[16][132];
    __shared__ int   s_midr[128], s_midc[128];
    __shared__ float s_mpv[128], s_mpt[128];
    __shared__ float s_nr[128], s_nc[128];

    int i0 = blockIdx.y * 128, j0 = blockIdx.x * 128;
    int tid = threadIdx.x;
    if (tid < 128) {
        s_midr[tid] = g_mid[i0 + tid];
        s_midc[tid] = g_mid[j0 + tid];
        s_mpv[tid]  = g_mpv[i0 + tid];
        s_mpt[tid]  = g_mpt[j0 + tid];
        s_nr[tid] = 0.0f; s_nc[tid] = 0.0f;
    }
    int lr = tid >> 1, lc = (tid & 1) * 8;
    int ty = tid >> 4, tx = tid & 15;
    float acc[8][8];
    #pragma unroll
    for (int r = 0; r < 8; r++)
        #pragma unroll
        for (int c = 0; c < 8; c++) acc[r][c] = 0.0f;
    for (int kt = 0; kt < D; kt += 16) {
        const float* pa = g_Vn + (size_t)(i0 + lr) * D + kt + lc;
        float4 a0 = *(const float4*)pa, a1 = *(const float4*)(pa + 4);
        const float* pb = g_Tn + (size_t)(j0 + lr) * D + kt + lc;
        float4 b0 = *(const float4*)pb, b1 = *(const float4*)(pb + 4);
        __syncthreads();
        As[lc+0][lr]=a0.x; As[lc+1][lr]=a0.y; As[lc+2][lr]=a0.z; As[lc+3][lr]=a0.w;
        As[lc+4][lr]=a1.x; As[lc+5][lr]=a1.y; As[lc+6][lr]=a1.z; As[lc+7][lr]=a1.w;
        Bs[lc+0][lr]=b0.x; Bs[lc+1][lr]=b0.y; Bs[lc+2][lr]=b0.z; Bs[lc+3][lr]=b0.w;
        Bs[lc+4][lr]=b1.x; Bs[lc+5][lr]=b1.y; Bs[lc+6][lr]=b1.z; Bs[lc+7][lr]=b1.w;
        __syncthreads();
        #pragma unroll
        for (int k = 0; k < 16; k++) {
            float4 fa0 = *(const float4*)&As[k][ty*8], fa1 = *(const float4*)&As[k][ty*8+4];
            float4 fb0 = *(const float4*)&Bs[k][tx*8], fb1 = *(const float4*)&Bs[k][tx*8+4];
            float ar[8] = {fa0.x,fa0.y,fa0.z,fa0.w,fa1.x,fa1.y,fa1.z,fa1.w};
            float br[8] = {fb0.x,fb0.y,fb0.z,fb0.w,fb1.x,fb1.y,fb1.z,fb1.w};
            #pragma unroll
            for (int r = 0; r < 8; r++)
                #pragma unroll
                for (int c = 0; c < 8; c++)
                    acc[r][c] = fmaf(ar[r], br[c], acc[r][c]);
        }
    }
    int midr[8], midc[8]; float mpvr[8], mptc[8];
    #pragma unroll
    for (int r = 0; r < 8; r++) { midr[r]=s_midr[ty*8+r]; mpvr[r]=s_mpv[ty*8+r]; }
    #pragma unroll
    for (int c = 0; c < 8; c++) { midc[c]=s_midc[tx*8+c]; mptc[c]=s_mpt[tx*8+c]; }
    float rs[8] = {0,0,0,0,0,0,0,0}, cs[8] = {0,0,0,0,0,0,0,0};
    #pragma unroll
    for (int r = 0; r < 8; r++)
        #pragma unroll
        for (int c = 0; c < 8; c++) {
            float sv = acc[r][c];
            float e = __expf(sv * c_INV_T);
            if (midr[r] != midc[c]) {
                rs[r] += e * ((sv < mpvr[r] && sv > mpvr[r] - c_MARGIN) ? 2.0f : 1.0f);
                cs[c] += e * ((sv < mptc[c] && sv > mptc[c] - c_MARGIN) ? 2.0f : 1.0f);
            }
        }
    #pragma unroll
    for (int r = 0; r < 8; r++) atomicAdd(&s_nr[ty*8+r], rs[r]);
    #pragma unroll
    for (int c = 0; c < 8; c++) atomicAdd(&s_nc[tx*8+c], cs[c]);
    __syncthreads();
    if (tid < 128) {
        atomicAdd(&g_negv[i0 + tid], s_nr[tid]);
        atomicAdd(&g_negt[j0 + tid], s_nc[tid]);
    }
}

// ---------------------------------------------------------------------------
// K5: finalize over pair list (thread per pair, grid-stride)
// ---------------------------------------------------------------------------
__global__ void k_final_pairs(int B) {
    int np = min(g_pcnt, NPAIR_MAX);
    int gid = blockIdx.x * blockDim.x + threadIdx.x;
    int stride = gridDim.x * blockDim.x;
    float ts = 0.0f;
    for (int p = gid; p < np; p += stride) {
        int2 pr = g_pairs[p];
        int i = pr.x;
        if (g_slow[i]) continue;
        int cnt = g_cnt[i];
        if (cnt <= 0 || cnt >= B) continue;
        float2 d = g_pd[p];
        ts += log1pf(g_negv[i] * __expf(-d.x * c_INV_T))
            + log1pf(g_negt[i] * __expf(-d.y * c_INV_T));
    }
    #pragma unroll
    for (int o = 16; o > 0; o >>= 1) ts += __shfl_xor_sync(0xffffffffu, ts, o);
    if ((threadIdx.x & 31) == 0 && ts != 0.0f) atomicAdd(&g_loss, ts);
}

// slow path finalize (warp per flagged row, full scan)
__global__ void k_final_slow(int B, int D) {
    int i = (blockIdx.x * blockDim.x + threadIdx.x) >> 5;
    if (i >= B || !g_slow[i]) return;
    int lane = threadIdx.x & 31;
    int cnt = g_cnt[i];
    if (cnt <= 0 || cnt >= B) return;
    int my = g_mid[i];
    const float* vi = g_Vn + (size_t)i * D;
    const float* ti = g_Tn + (size_t)i * D;
    float nv = g_negv[i], nt = g_negt[i];
    float ts = 0.0f;
    for (int j = 0; j < B; j++) {
        if (g_mid[j] != my) continue;
        const float* tj = g_Tn + (size_t)j * D;
        const float* vj = g_Vn + (size_t)j * D;
        float dv = 0.0f, dt = 0.0f;
        for (int idx = lane * 4; idx < D; idx += 128) {
            float4 a = *(const float4*)(vi + idx), bb = *(const float4*)(tj + idx);
            dv += a.x * bb.x + a.y * bb.y + a.z * bb.z + a.w * bb.w;
            float4 c = *(const float4*)(ti + idx), d = *(const float4*)(vj + idx);
            dt += c.x * d.x + c.y * d.y + c.z * d.z + c.w * d.w;
        }
        #pragma unroll
        for (int o = 16; o > 0; o >>= 1) {
            dv += __shfl_xor_sync(0xffffffffu, dv, o);
            dt += __shfl_xor_sync(0xffffffffu, dt, o);
        }
        ts += log1pf(nv * __expf(-dv * c_INV_T)) + log1pf(nt * __expf(-dt * c_INV_T));
    }
    if (lane == 0) atomicAdd(&g_loss, ts);
}

__global__ void k_out(float* out) {
    if (threadIdx.x == 0) {
        float np = (float)g_npos;
        out[0] = (g_npos > 0) ? g_loss / (2.0f * fmaxf(np, 1.0f)) : 0.0f;
    }
}

// ---------------------------------------------------------------------------
extern "C" void kernel_launch(void* const* d_in, const int* in_sizes, int n_in,
                              void* d_out, int out_size) {
    const float* V = (const float*)d_in[0];
    const float* T = (const float*)d_in[1];
    const unsigned int* ids = (const unsigned int*)d_in[2];
    int B = in_sizes[2];
    int D = in_sizes[0] / B;

    k_ids<<<1, 256>>>(ids, B);
    k_zero<<<(B + 255) / 256, 256>>>(B);
    dim3 gn(B, 2);
    k_norm<<<gn, 128>>>(V, T, D);
    k_pairs<<<(B + 255) / 256, 256>>>(B);
    k_pdots<<<256, 256>>>(B, D);
    k_mean<<<(B + 255) / 256, 256>>>(B);
    k_pos_slow<<<(B + 7) / 8, 256>>>(B, D);

    bool tc_ok = (B % 128 == 0) && (D % 64 == 0) && (D >= 64) &&
                 (B <= B_MAX) && (D <= D_MAX);
    if (tc_ok) {
        const int DYN = 2 * ISTG;  // 81920
        cudaFuncSetAttribute(k_sim_imma, cudaFuncAttributeMaxDynamicSharedMemorySize, DYN);
        dim3 g3(B / 128, B / 128);
        k_sim_imma<<<g3, 256, DYN>>>(B, D);
    } else {
        dim3 g3((B + 127) / 128, (B + 127) / 128);
        k_sim_simt<<<g3, 256>>>(B, D);
    }
    k_final_pairs<<<256, 256>>>(B);
    k_final_slow<<<(B + 7) / 8, 256>>>(B, D);
    k_out<<<1, 32>>>((float*)d_out);
}